// round 14
// baseline (speedup 1.0000x reference)
#include <cuda_runtime.h>
#include <cuda_fp16.h>

#define NN   10000
#define EE   640000
#define KDIM 128
#define CAP  160

#define SCAT_BLOCKS 625             // 625*256*4 = 640000 edges
#define RB          313             // ceil(10000/32) row blocks of 32
#define G0_BLOCKS   (RB * 2)        // layer-0: 313 x 2 col-blocks of 64
#define FUSED_BLOCKS (SCAT_BLOCKS + G0_BLOCKS)
#define AGG_BLOCKS  1250            // 10000 warps

// prep block ranges: zero counters + W0/W1/W2 -> fp16
#define PREP_CNT 10
#define PREP_W0  (PREP_CNT + 16)    // 128*128 f32 = 4096 float4
#define PREP_W1  (PREP_W0 + 16)
#define PREP_W2  (PREP_W1 + 8)      // 128*64 f32 = 2048 float4

#define APAD 136                    // A-tile smem row stride (halves)
#define BPAD64  72                  // B-tile stride for 64-wide B
#define BPAD128 136                 // B-tile stride for 128-wide B

// ---------------- scratch (device globals, no allocation) ----------------
__device__ int    g_cnt[NN];
__device__ int    g_eb[NN * CAP];
__device__ __half g_zh0[NN * KDIM];
__device__ __half g_zh1[NN * KDIM];
__device__ __half g_zh2[NN * 64];
__device__ __half g_h16[NN * KDIM];        // agg output (next GEMM A operand)
__device__ __half g_w0h[KDIM * KDIM];
__device__ __half g_w1h[KDIM * KDIM];
__device__ __half g_w2h[KDIM * 64];

__device__ __forceinline__ __half2 u2h(unsigned u) { return *reinterpret_cast<__half2*>(&u); }

__device__ __forceinline__ uint2 f4_to_h4(float4 v) {
    __half2 h0 = __floats2half2_rn(v.x, v.y);
    __half2 h1 = __floats2half2_rn(v.z, v.w);
    uint2 r;
    r.x = *(unsigned*)&h0;
    r.y = *(unsigned*)&h1;
    return r;
}

__device__ __forceinline__ float4 h4_to_f4(uint2 r) {
    float2 f0 = __half22float2(u2h(r.x));
    float2 f1 = __half22float2(u2h(r.y));
    return make_float4(f0.x, f0.y, f1.x, f1.y);
}

// ---------------- prep: zero counters + W0/W1/W2 -> fp16 ----------------
__global__ void prep_kernel(const float* __restrict__ W0, const float* __restrict__ W1,
                            const float* __restrict__ W2) {
    int b = blockIdx.x, t = threadIdx.x;
    if (b < PREP_CNT) {
        int i = b * 256 + t;
        if (i < NN / 4) ((int4*)g_cnt)[i] = make_int4(0, 0, 0, 0);
    } else if (b < PREP_W0) {
        int i = (b - PREP_CNT) * 256 + t;
        ((uint2*)g_w0h)[i] = f4_to_h4(((const float4*)W0)[i]);
    } else if (b < PREP_W1) {
        int i = (b - PREP_W0) * 256 + t;
        ((uint2*)g_w1h)[i] = f4_to_h4(((const float4*)W1)[i]);
    } else {
        int i = (b - PREP_W1) * 256 + t;
        ((uint2*)g_w2h)[i] = f4_to_h4(((const float4*)W2)[i]);
    }
}

// ---------------- mma helpers ----------------
__device__ __forceinline__ unsigned smem_u32(const void* p) {
    return (unsigned)__cvta_generic_to_shared(p);
}
__device__ __forceinline__ void ldsm_x4(unsigned& r0, unsigned& r1, unsigned& r2, unsigned& r3,
                                        unsigned addr) {
    asm volatile("ldmatrix.sync.aligned.m8n8.x4.shared.b16 {%0,%1,%2,%3}, [%4];"
                 : "=r"(r0), "=r"(r1), "=r"(r2), "=r"(r3) : "r"(addr));
}
__device__ __forceinline__ void ldsm_x4_t(unsigned& r0, unsigned& r1, unsigned& r2, unsigned& r3,
                                          unsigned addr) {
    asm volatile("ldmatrix.sync.aligned.m8n8.x4.trans.shared.b16 {%0,%1,%2,%3}, [%4];"
                 : "=r"(r0), "=r"(r1), "=r"(r2), "=r"(r3) : "r"(addr));
}
__device__ __forceinline__ void mma_16816(float* c, unsigned a0, unsigned a1, unsigned a2,
                                          unsigned a3, unsigned b0, unsigned b1) {
    asm volatile(
        "mma.sync.aligned.m16n8k16.row.col.f32.f16.f16.f32 "
        "{%0,%1,%2,%3}, {%4,%5,%6,%7}, {%8,%9}, {%0,%1,%2,%3};"
        : "+f"(c[0]), "+f"(c[1]), "+f"(c[2]), "+f"(c[3])
        : "r"(a0), "r"(a1), "r"(a2), "r"(a3), "r"(b0), "r"(b1));
}

// Generic warp MMA tile: 16 rows x (NH*16) cols, K=128, fp16 epilogue.
template <int NH, int BST>
__device__ __forceinline__ void mma_warp_tile(const __half* As, const __half* Bs,
                                              __half* __restrict__ zhout,
                                              int M, int Nc, int bm, int bn,
                                              int wm, int wn) {
    int lane = threadIdx.x & 31;
    float c[2 * NH][4] = {};
    int jhi = lane >> 3;
#pragma unroll
    for (int ks = 0; ks < 8; ks++) {
        unsigned a0, a1, a2, a3;
        ldsm_x4(a0, a1, a2, a3,
                smem_u32(As + (wm + (lane & 15)) * APAD + (lane >> 4) * 8 + ks * 16));
#pragma unroll
        for (int nh = 0; nh < NH; nh++) {
            int krow = ks * 16 + (jhi & 1) * 8 + (lane & 7);
            int ncol = wn + nh * 16 + (jhi >> 1) * 8;
            unsigned b0, b1, b2, b3;
            ldsm_x4_t(b0, b1, b2, b3, smem_u32(Bs + krow * BST + ncol));
            mma_16816(c[2 * nh + 0], a0, a1, a2, a3, b0, b1);
            mma_16816(c[2 * nh + 1], a0, a1, a2, a3, b2, b3);
        }
    }
    int r0 = bm + wm + (lane >> 2);
    int col0 = bn + wn + (lane & 3) * 2;
#pragma unroll
    for (int t = 0; t < 2 * NH; t++) {
        int col = col0 + t * 8;
        if (r0 < M)
            *(__half2*)(zhout + (size_t)r0 * Nc + col) = __floats2half2_rn(c[t][0], c[t][1]);
        int r1 = r0 + 8;
        if (r1 < M)
            *(__half2*)(zhout + (size_t)r1 * Nc + col) = __floats2half2_rn(c[t][2], c[t][3]);
    }
}

// ---------------- layer-0 GEMM body (fp32 A inline cvt, fp16 W0) ----------------
__device__ __forceinline__ void gemm0_body(const float* __restrict__ feat, int bm, int bn) {
    __shared__ __half As[32 * APAD];
    __shared__ __half Bs[128 * BPAD64];
    int tid = threadIdx.x;
    // A: 32 rows x 128 f32 -> fp16 (1024 float4)
#pragma unroll
    for (int i = 0; i < 4; i++) {
        int idx = tid + i * 256;
        int row = idx >> 5, c4 = idx & 31;
        int grow = bm + row;
        float4 v = make_float4(0, 0, 0, 0);
        if (grow < NN) v = *(const float4*)(feat + (size_t)grow * KDIM + c4 * 4);
        *(uint2*)(As + row * APAD + c4 * 4) = f4_to_h4(v);
    }
    // B: fp16 W0 slice, 128 rows x 64 halves = 1024 uint4
#pragma unroll
    for (int i = 0; i < 4; i++) {
        int idx = tid + i * 256;
        int row = idx >> 3, c8 = idx & 7;
        uint4 v = *(const uint4*)(g_w0h + (size_t)row * KDIM + bn + c8 * 8);
        *(uint4*)(Bs + row * BPAD64 + c8 * 8) = v;
    }
    __syncthreads();
    int wid = tid >> 5;
    mma_warp_tile<1, BPAD64>(As, Bs, g_zh0, NN, 128, bm, bn, (wid & 1) * 16, (wid >> 1) * 16);
}

// ---------------- fused: bucket scatter || layer-0 GEMM ----------------
__global__ void fused_l0_kernel(const float* __restrict__ feat,
                                const int* __restrict__ src, const int* __restrict__ dst) {
    int b = blockIdx.x;
    if (b < SCAT_BLOCKS) {
        int t = b * blockDim.x + threadIdx.x;   // one thread = 4 edges
        int4 dv = ((const int4*)dst)[t];
        int4 sv = ((const int4*)src)[t];
        int p0 = atomicAdd(&g_cnt[dv.x], 1);
        int p1 = atomicAdd(&g_cnt[dv.y], 1);
        int p2 = atomicAdd(&g_cnt[dv.z], 1);
        int p3 = atomicAdd(&g_cnt[dv.w], 1);
        g_eb[dv.x * CAP + p0] = sv.x;
        g_eb[dv.y * CAP + p1] = sv.y;
        g_eb[dv.z * CAP + p2] = sv.z;
        g_eb[dv.w * CAP + p3] = sv.w;
    } else {
        int gb = b - SCAT_BLOCKS;
        gemm0_body(feat, (gb >> 1) * 32, (gb & 1) * 64);
    }
}

// ---------------- layer-1 GEMM: 32x128 tile (full N), fp16 in/out ----------------
__global__ void gemm_n128_kernel(const __half* __restrict__ A16, const __half* __restrict__ B16,
                                 __half* __restrict__ zhout) {
    __shared__ __half As[32 * APAD];
    __shared__ __half Bs[128 * BPAD128];
    int tid = threadIdx.x;
    int bm = blockIdx.x * 32;
    // A: 32 rows x 128 halves = 512 uint4
#pragma unroll
    for (int i = 0; i < 2; i++) {
        int idx = tid + i * 256;
        int row = idx >> 4, c8 = idx & 15;
        int grow = bm + row;
        uint4 v = make_uint4(0, 0, 0, 0);
        if (grow < NN) v = *(const uint4*)(A16 + (size_t)grow * KDIM + c8 * 8);
        *(uint4*)(As + row * APAD + c8 * 8) = v;
    }
    // B: 128 x 128 halves = 2048 uint4
#pragma unroll
    for (int i = 0; i < 8; i++) {
        int idx = tid + i * 256;
        int row = idx >> 4, c8 = idx & 15;
        uint4 v = *(const uint4*)(B16 + (size_t)row * KDIM + c8 * 8);
        *(uint4*)(Bs + row * BPAD128 + c8 * 8) = v;
    }
    __syncthreads();
    int wid = tid >> 5;
    mma_warp_tile<2, BPAD128>(As, Bs, zhout, NN, 128, bm, 0, (wid & 1) * 16, (wid >> 1) * 32);
}

// ---------------- layer-2 GEMM: 32x64 tile, fp16 in/out ----------------
__global__ void gemm_n64_kernel(const __half* __restrict__ A16, const __half* __restrict__ B16,
                                __half* __restrict__ zhout) {
    __shared__ __half As[32 * APAD];
    __shared__ __half Bs[128 * BPAD64];
    int tid = threadIdx.x;
    int bm = blockIdx.x * 32;
#pragma unroll
    for (int i = 0; i < 2; i++) {
        int idx = tid + i * 256;
        int row = idx >> 4, c8 = idx & 15;
        int grow = bm + row;
        uint4 v = make_uint4(0, 0, 0, 0);
        if (grow < NN) v = *(const uint4*)(A16 + (size_t)grow * KDIM + c8 * 8);
        *(uint4*)(As + row * APAD + c8 * 8) = v;
    }
#pragma unroll
    for (int i = 0; i < 4; i++) {
        int idx = tid + i * 256;
        int row = idx >> 3, c8 = idx & 7;
        uint4 v = *(const uint4*)(B16 + (size_t)row * 64 + c8 * 8);
        *(uint4*)(Bs + row * BPAD64 + c8 * 8) = v;
    }
    __syncthreads();
    int wid = tid >> 5;
    mma_warp_tile<1, BPAD64>(As, Bs, zhout, NN, 64, bm, 0, (wid & 1) * 16, (wid >> 1) * 16);
}

// ---------------- aggregation helpers ----------------
__device__ __forceinline__ void accum_tree4_128(float4& acc, uint2 a, uint2 b, uint2 c, uint2 d) {
    __half2 gx = __hadd2(__hadd2(u2h(a.x), u2h(b.x)), __hadd2(u2h(c.x), u2h(d.x)));
    __half2 gy = __hadd2(__hadd2(u2h(a.y), u2h(b.y)), __hadd2(u2h(c.y), u2h(d.y)));
    float2 f0 = __half22float2(gx);
    float2 f1 = __half22float2(gy);
    acc.x += f0.x; acc.y += f0.y; acc.z += f1.x; acc.w += f1.y;
}
__device__ __forceinline__ void accum_tree4_64(float2& acc, unsigned a, unsigned b,
                                               unsigned c, unsigned d) {
    __half2 g = __hadd2(__hadd2(u2h(a), u2h(b)), __hadd2(u2h(c), u2h(d)));
    float2 f = __half22float2(g);
    acc.x += f.x; acc.y += f.y;
}

// ---------------- aggregation (128 cols): h16[v] = zh[v] + sum zh[u] ----------------
// warp/row, 16-edge unroll: 4 fp16 trees -> 4 fp32 accumulator chains, MLP=16.
__global__ void agg128_kernel(const __half* __restrict__ zh, __half* __restrict__ outh) {
    int gw = (blockIdx.x * blockDim.x + threadIdx.x) >> 5;
    if (gw >= NN) return;
    int lane = threadIdx.x & 31;
    const uint2* zh2 = (const uint2*)zh;

    float4 self = h4_to_f4(zh2[gw * 32 + lane]);
    float4 aA = make_float4(0, 0, 0, 0);
    float4 aB = make_float4(0, 0, 0, 0);
    float4 aC = make_float4(0, 0, 0, 0);
    float4 aD = make_float4(0, 0, 0, 0);

    int n = g_cnt[gw];
    int s = gw * CAP;
    int j = 0;
    for (; j + 16 <= n; j += 16) {
        int4 i0 = *(const int4*)&g_eb[s + j];
        int4 i1 = *(const int4*)&g_eb[s + j + 4];
        int4 i2 = *(const int4*)&g_eb[s + j + 8];
        int4 i3 = *(const int4*)&g_eb[s + j + 12];
        uint2 v0  = zh2[i0.x * 32 + lane];
        uint2 v1  = zh2[i0.y * 32 + lane];
        uint2 v2  = zh2[i0.z * 32 + lane];
        uint2 v3  = zh2[i0.w * 32 + lane];
        uint2 v4  = zh2[i1.x * 32 + lane];
        uint2 v5  = zh2[i1.y * 32 + lane];
        uint2 v6  = zh2[i1.z * 32 + lane];
        uint2 v7  = zh2[i1.w * 32 + lane];
        uint2 v8  = zh2[i2.x * 32 + lane];
        uint2 v9  = zh2[i2.y * 32 + lane];
        uint2 v10 = zh2[i2.z * 32 + lane];
        uint2 v11 = zh2[i2.w * 32 + lane];
        uint2 v12 = zh2[i3.x * 32 + lane];
        uint2 v13 = zh2[i3.y * 32 + lane];
        uint2 v14 = zh2[i3.z * 32 + lane];
        uint2 v15 = zh2[i3.w * 32 + lane];
        accum_tree4_128(aA, v0, v1, v2, v3);
        accum_tree4_128(aB, v4, v5, v6, v7);
        accum_tree4_128(aC, v8, v9, v10, v11);
        accum_tree4_128(aD, v12, v13, v14, v15);
    }
    for (; j + 8 <= n; j += 8) {
        int4 i0 = *(const int4*)&g_eb[s + j];
        int4 i1 = *(const int4*)&g_eb[s + j + 4];
        uint2 v0 = zh2[i0.x * 32 + lane];
        uint2 v1 = zh2[i0.y * 32 + lane];
        uint2 v2 = zh2[i0.z * 32 + lane];
        uint2 v3 = zh2[i0.w * 32 + lane];
        uint2 v4 = zh2[i1.x * 32 + lane];
        uint2 v5 = zh2[i1.y * 32 + lane];
        uint2 v6 = zh2[i1.z * 32 + lane];
        uint2 v7 = zh2[i1.w * 32 + lane];
        accum_tree4_128(aA, v0, v1, v2, v3);
        accum_tree4_128(aB, v4, v5, v6, v7);
    }
    for (; j < n; j++) {
        uint2 v = zh2[g_eb[s + j] * 32 + lane];
        float2 f0 = __half22float2(u2h(v.x));
        float2 f1 = __half22float2(u2h(v.y));
        aA.x += f0.x; aA.y += f0.y; aA.z += f1.x; aA.w += f1.y;
    }
    float rx = self.x + (aA.x + aB.x) + (aC.x + aD.x);
    float ry = self.y + (aA.y + aB.y) + (aC.y + aD.y);
    float rz = self.z + (aA.z + aB.z) + (aC.z + aD.z);
    float rw = self.w + (aA.w + aB.w) + (aC.w + aD.w);
    __half2 h0 = __floats2half2_rn(rx, ry);
    __half2 h1 = __floats2half2_rn(rz, rw);
    uint2 hp;
    hp.x = *(unsigned*)&h0;
    hp.y = *(unsigned*)&h1;
    ((uint2*)outh)[gw * 32 + lane] = hp;
}

// ---------------- final aggregation (64 cols) -> fp32 out ----------------
__global__ void agg64_kernel(const __half* __restrict__ zh, float* __restrict__ out) {
    int gw = (blockIdx.x * blockDim.x + threadIdx.x) >> 5;
    if (gw >= NN) return;
    int lane = threadIdx.x & 31;
    const unsigned* zhu = (const unsigned*)zh;

    float2 self = __half22float2(u2h(zhu[gw * 32 + lane]));
    float2 aA = make_float2(0, 0);
    float2 aB = make_float2(0, 0);
    float2 aC = make_float2(0, 0);
    float2 aD = make_float2(0, 0);

    int n = g_cnt[gw];
    int s = gw * CAP;
    int j = 0;
    for (; j + 16 <= n; j += 16) {
        int4 i0 = *(const int4*)&g_eb[s + j];
        int4 i1 = *(const int4*)&g_eb[s + j + 4];
        int4 i2 = *(const int4*)&g_eb[s + j + 8];
        int4 i3 = *(const int4*)&g_eb[s + j + 12];
        unsigned v0  = zhu[i0.x * 32 + lane];
        unsigned v1  = zhu[i0.y * 32 + lane];
        unsigned v2  = zhu[i0.z * 32 + lane];
        unsigned v3  = zhu[i0.w * 32 + lane];
        unsigned v4  = zhu[i1.x * 32 + lane];
        unsigned v5  = zhu[i1.y * 32 + lane];
        unsigned v6  = zhu[i1.z * 32 + lane];
        unsigned v7  = zhu[i1.w * 32 + lane];
        unsigned v8  = zhu[i2.x * 32 + lane];
        unsigned v9  = zhu[i2.y * 32 + lane];
        unsigned v10 = zhu[i2.z * 32 + lane];
        unsigned v11 = zhu[i2.w * 32 + lane];
        unsigned v12 = zhu[i3.x * 32 + lane];
        unsigned v13 = zhu[i3.y * 32 + lane];
        unsigned v14 = zhu[i3.z * 32 + lane];
        unsigned v15 = zhu[i3.w * 32 + lane];
        accum_tree4_64(aA, v0, v1, v2, v3);
        accum_tree4_64(aB, v4, v5, v6, v7);
        accum_tree4_64(aC, v8, v9, v10, v11);
        accum_tree4_64(aD, v12, v13, v14, v15);
    }
    for (; j + 8 <= n; j += 8) {
        int4 i0 = *(const int4*)&g_eb[s + j];
        int4 i1 = *(const int4*)&g_eb[s + j + 4];
        unsigned v0 = zhu[i0.x * 32 + lane];
        unsigned v1 = zhu[i0.y * 32 + lane];
        unsigned v2 = zhu[i0.z * 32 + lane];
        unsigned v3 = zhu[i0.w * 32 + lane];
        unsigned v4 = zhu[i1.x * 32 + lane];
        unsigned v5 = zhu[i1.y * 32 + lane];
        unsigned v6 = zhu[i1.z * 32 + lane];
        unsigned v7 = zhu[i1.w * 32 + lane];
        accum_tree4_64(aA, v0, v1, v2, v3);
        accum_tree4_64(aB, v4, v5, v6, v7);
    }
    for (; j < n; j++) {
        float2 f = __half22float2(u2h(zhu[g_eb[s + j] * 32 + lane]));
        aA.x += f.x; aA.y += f.y;
    }
    float2 r;
    r.x = self.x + (aA.x + aB.x) + (aC.x + aD.x);
    r.y = self.y + (aA.y + aB.y) + (aC.y + aD.y);
    ((float2*)out)[gw * 32 + lane] = r;
}

// ---------------- launch ----------------
extern "C" void kernel_launch(void* const* d_in, const int* in_sizes, int n_in,
                              void* d_out, int out_size) {
    const float* feat = (const float*)d_in[0];
    const float* W0   = (const float*)d_in[1];
    const float* W1   = (const float*)d_in[2];
    const float* W2   = (const float*)d_in[3];
    const int*   src  = (const int*)d_in[4];
    const int*   dst  = (const int*)d_in[5];
    float*       out  = (float*)d_out;

    void *pzh0, *pzh1, *pzh2, *ph16, *pw1, *pw2;
    cudaGetSymbolAddress(&pzh0, g_zh0);
    cudaGetSymbolAddress(&pzh1, g_zh1);
    cudaGetSymbolAddress(&pzh2, g_zh2);
    cudaGetSymbolAddress(&ph16, g_h16);
    cudaGetSymbolAddress(&pw1, g_w1h);
    cudaGetSymbolAddress(&pw2, g_w2h);
    __half* h16 = (__half*)ph16;

    // prep: zero counters + W0/W1/W2 -> fp16
    prep_kernel<<<PREP_W2, 256>>>(W0, W1, W2);
    // scatter || layer-0 GEMM (fp16 W0) -> zh0
    fused_l0_kernel<<<FUSED_BLOCKS, 256>>>(feat, src, dst);
    // layer 1: agg(zh0) -> h16 ; h16 @ W1 -> zh1 (full-N tiles)
    agg128_kernel<<<AGG_BLOCKS, 256>>>((const __half*)pzh0, h16);
    gemm_n128_kernel<<<RB, 256>>>(h16, (const __half*)pw1, (__half*)pzh1);
    // layer 2: agg(zh1) -> h16 ; h16 @ W2 -> zh2 (64 cols)
    agg128_kernel<<<AGG_BLOCKS, 256>>>((const __half*)pzh1, h16);
    gemm_n64_kernel<<<RB, 256>>>(h16, (const __half*)pw2, (__half*)pzh2);
    // final aggregation -> fp32 out
    agg64_kernel<<<AGG_BLOCKS, 256>>>((const __half*)pzh2, out);
}

// round 15
// speedup vs baseline: 1.3723x; 1.3723x over previous
#include <cuda_runtime.h>
#include <cuda_fp16.h>

#define NN   10000
#define EE   640000
#define KDIM 128
#define CAP  160

#define SCAT_BLOCKS 625             // 625*256*4 = 640000 edges
#define RB          313             // ceil(10000/32) row blocks of 32
#define G0_BLOCKS   (RB * 2)        // layer-0: 313 x 2 col-blocks of 64
#define WC1_BLOCKS  16              // W1: 128*128 f32 = 4096 float4
#define WC2_BLOCKS  8               // W2: 128*64  f32 = 2048 float4
#define FUSED_BLOCKS (SCAT_BLOCKS + G0_BLOCKS + WC1_BLOCKS + WC2_BLOCKS)
#define AGG_BLOCKS  1250            // 10000 warps

// prep: zero counters + W0 -> fp16
#define PREP_CNT 10
#define PREP_W0  (PREP_CNT + 16)    // 128*128 f32 = 4096 float4

#define APAD 136                    // A-tile smem row stride (halves)
#define BPAD 72                     // B-tile smem row stride (64 + 8)

// ---------------- scratch (device globals, no allocation) ----------------
__device__ int    g_cnt[NN];
__device__ int    g_eb[NN * CAP];
__device__ __half g_zh0[NN * KDIM];
__device__ __half g_zh1[NN * KDIM];
__device__ __half g_zh2[NN * 64];
__device__ __half g_h16[NN * KDIM];        // agg output (next GEMM A operand)
__device__ __half g_w0h[KDIM * KDIM];
__device__ __half g_w1h[KDIM * KDIM];
__device__ __half g_w2h[KDIM * 64];

__device__ __forceinline__ __half2 u2h(unsigned u) { return *reinterpret_cast<__half2*>(&u); }

__device__ __forceinline__ uint2 f4_to_h4(float4 v) {
    __half2 h0 = __floats2half2_rn(v.x, v.y);
    __half2 h1 = __floats2half2_rn(v.z, v.w);
    uint2 r;
    r.x = *(unsigned*)&h0;
    r.y = *(unsigned*)&h1;
    return r;
}

__device__ __forceinline__ float4 h4_to_f4(uint2 r) {
    float2 f0 = __half22float2(u2h(r.x));
    float2 f1 = __half22float2(u2h(r.y));
    return make_float4(f0.x, f0.y, f1.x, f1.y);
}

// ---------------- prep: zero counters + W0 -> fp16 ----------------
__global__ void prep_kernel(const float* __restrict__ W0) {
    int b = blockIdx.x, t = threadIdx.x;
    if (b < PREP_CNT) {
        int i = b * 256 + t;
        if (i < NN / 4) ((int4*)g_cnt)[i] = make_int4(0, 0, 0, 0);
    } else {
        int i = (b - PREP_CNT) * 256 + t;
        ((uint2*)g_w0h)[i] = f4_to_h4(((const float4*)W0)[i]);
    }
}

// ---------------- mma helpers ----------------
__device__ __forceinline__ unsigned smem_u32(const void* p) {
    return (unsigned)__cvta_generic_to_shared(p);
}
__device__ __forceinline__ void ldsm_x4(unsigned& r0, unsigned& r1, unsigned& r2, unsigned& r3,
                                        unsigned addr) {
    asm volatile("ldmatrix.sync.aligned.m8n8.x4.shared.b16 {%0,%1,%2,%3}, [%4];"
                 : "=r"(r0), "=r"(r1), "=r"(r2), "=r"(r3) : "r"(addr));
}
__device__ __forceinline__ void ldsm_x4_t(unsigned& r0, unsigned& r1, unsigned& r2, unsigned& r3,
                                          unsigned addr) {
    asm volatile("ldmatrix.sync.aligned.m8n8.x4.trans.shared.b16 {%0,%1,%2,%3}, [%4];"
                 : "=r"(r0), "=r"(r1), "=r"(r2), "=r"(r3) : "r"(addr));
}
__device__ __forceinline__ void mma_16816(float* c, unsigned a0, unsigned a1, unsigned a2,
                                          unsigned a3, unsigned b0, unsigned b1) {
    asm volatile(
        "mma.sync.aligned.m16n8k16.row.col.f32.f16.f16.f32 "
        "{%0,%1,%2,%3}, {%4,%5,%6,%7}, {%8,%9}, {%0,%1,%2,%3};"
        : "+f"(c[0]), "+f"(c[1]), "+f"(c[2]), "+f"(c[3])
        : "r"(a0), "r"(a1), "r"(a2), "r"(a3), "r"(b0), "r"(b1));
}

// MMA mainloop + fp16 epilogue: 32x64 tile, 8 warps (16x16 warp tiles)
__device__ __forceinline__ void mma_tile_32x64(const __half* As, const __half* Bs,
                                               __half* __restrict__ zhout,
                                               int M, int Nc, int bm, int bn) {
    int tid = threadIdx.x;
    int wid = tid >> 5, lane = tid & 31;
    int wm = (wid & 1) * 16;
    int wn = (wid >> 1) * 16;
    float c[2][4] = {};
    int jhi = lane >> 3;
#pragma unroll
    for (int ks = 0; ks < 8; ks++) {
        unsigned a0, a1, a2, a3;
        ldsm_x4(a0, a1, a2, a3,
                smem_u32(As + (wm + (lane & 15)) * APAD + (lane >> 4) * 8 + ks * 16));
        int krow = ks * 16 + (jhi & 1) * 8 + (lane & 7);
        int ncol = wn + (jhi >> 1) * 8;
        unsigned b0, b1, b2, b3;
        ldsm_x4_t(b0, b1, b2, b3, smem_u32(Bs + krow * BPAD + ncol));
        mma_16816(c[0], a0, a1, a2, a3, b0, b1);
        mma_16816(c[1], a0, a1, a2, a3, b2, b3);
    }
    int r0 = bm + wm + (lane >> 2);
    int col0 = bn + wn + (lane & 3) * 2;
#pragma unroll
    for (int t = 0; t < 2; t++) {
        int col = col0 + t * 8;
        if (r0 < M)
            *(__half2*)(zhout + (size_t)r0 * Nc + col) = __floats2half2_rn(c[t][0], c[t][1]);
        int r1 = r0 + 8;
        if (r1 < M)
            *(__half2*)(zhout + (size_t)r1 * Nc + col) = __floats2half2_rn(c[t][2], c[t][3]);
    }
}

// ---------------- layer-0 GEMM body (fp32 A inline cvt, fp16 W0) ----------------
__device__ __forceinline__ void gemm0_body(const float* __restrict__ feat, int bm, int bn) {
    __shared__ __half As[32 * APAD];
    __shared__ __half Bs[128 * BPAD];
    int tid = threadIdx.x;
    // A: 32 rows x 128 f32 -> fp16 (1024 float4)
#pragma unroll
    for (int i = 0; i < 4; i++) {
        int idx = tid + i * 256;
        int row = idx >> 5, c4 = idx & 31;
        int grow = bm + row;
        float4 v = make_float4(0, 0, 0, 0);
        if (grow < NN) v = *(const float4*)(feat + (size_t)grow * KDIM + c4 * 4);
        *(uint2*)(As + row * APAD + c4 * 4) = f4_to_h4(v);
    }
    // B: fp16 W0 slice, 128 rows x 64 halves = 1024 uint4
#pragma unroll
    for (int i = 0; i < 4; i++) {
        int idx = tid + i * 256;
        int row = idx >> 3, c8 = idx & 7;
        uint4 v = *(const uint4*)(g_w0h + (size_t)row * KDIM + bn + c8 * 8);
        *(uint4*)(Bs + row * BPAD + c8 * 8) = v;
    }
    __syncthreads();
    mma_tile_32x64(As, Bs, g_zh0, NN, 128, bm, bn);
}

// ---------------- fused: scatter || layer-0 GEMM || W1/W2 cvt ----------------
__global__ void fused_l0_kernel(const float* __restrict__ feat,
                                const float* __restrict__ W1, const float* __restrict__ W2,
                                const int* __restrict__ src, const int* __restrict__ dst) {
    int b = blockIdx.x;
    if (b < SCAT_BLOCKS) {
        int t = b * blockDim.x + threadIdx.x;   // one thread = 4 edges
        int4 dv = ((const int4*)dst)[t];
        int4 sv = ((const int4*)src)[t];
        int p0 = atomicAdd(&g_cnt[dv.x], 1);
        int p1 = atomicAdd(&g_cnt[dv.y], 1);
        int p2 = atomicAdd(&g_cnt[dv.z], 1);
        int p3 = atomicAdd(&g_cnt[dv.w], 1);
        g_eb[dv.x * CAP + p0] = sv.x;
        g_eb[dv.y * CAP + p1] = sv.y;
        g_eb[dv.z * CAP + p2] = sv.z;
        g_eb[dv.w * CAP + p3] = sv.w;
    } else if (b < SCAT_BLOCKS + G0_BLOCKS) {
        int gb = b - SCAT_BLOCKS;
        gemm0_body(feat, (gb >> 1) * 32, (gb & 1) * 64);
    } else if (b < SCAT_BLOCKS + G0_BLOCKS + WC1_BLOCKS) {
        int i = (b - SCAT_BLOCKS - G0_BLOCKS) * 256 + threadIdx.x;
        ((uint2*)g_w1h)[i] = f4_to_h4(((const float4*)W1)[i]);
    } else {
        int i = (b - SCAT_BLOCKS - G0_BLOCKS - WC1_BLOCKS) * 256 + threadIdx.x;
        ((uint2*)g_w2h)[i] = f4_to_h4(((const float4*)W2)[i]);
    }
}

// ---------------- GEMM (fp16 A, fp16 B) -> fp16 out, 32x64 tiles ----------------
__global__ void gemm_mma_kernel(const __half* __restrict__ A16, const __half* __restrict__ B16,
                                __half* __restrict__ zhout, int M, int Nc) {
    __shared__ __half As[32 * APAD];
    __shared__ __half Bs[128 * BPAD];
    int tid = threadIdx.x;
    int bm = blockIdx.x * 32, bn = blockIdx.y * 64;
    // A: 32 rows x 128 halves = 512 uint4
#pragma unroll
    for (int i = 0; i < 2; i++) {
        int idx = tid + i * 256;
        int row = idx >> 4, c8 = idx & 15;
        int grow = bm + row;
        uint4 v = make_uint4(0, 0, 0, 0);
        if (grow < M) v = *(const uint4*)(A16 + (size_t)grow * KDIM + c8 * 8);
        *(uint4*)(As + row * APAD + c8 * 8) = v;
    }
    // B: 128 rows x 64 halves = 1024 uint4
#pragma unroll
    for (int i = 0; i < 4; i++) {
        int idx = tid + i * 256;
        int row = idx >> 3, c8 = idx & 7;
        uint4 v = *(const uint4*)(B16 + (size_t)row * Nc + bn + c8 * 8);
        *(uint4*)(Bs + row * BPAD + c8 * 8) = v;
    }
    __syncthreads();
    mma_tile_32x64(As, Bs, zhout, M, Nc, bm, bn);
}

// ---------------- aggregation (128 cols): h16[v] = zh[v] + sum zh[u] ----------------
__global__ void agg128_kernel(const __half* __restrict__ zh, __half* __restrict__ outh) {
    int gw = (blockIdx.x * blockDim.x + threadIdx.x) >> 5;
    if (gw >= NN) return;
    int lane = threadIdx.x & 31;
    const uint2* zh2 = (const uint2*)zh;

    float4 self = h4_to_f4(zh2[gw * 32 + lane]);
    float4 aA = make_float4(0, 0, 0, 0);
    float4 aB = make_float4(0, 0, 0, 0);

    int n = g_cnt[gw];
    int s = gw * CAP;
    int j = 0;
    for (; j + 8 <= n; j += 8) {
        int4 i0 = *(const int4*)&g_eb[s + j];
        int4 i1 = *(const int4*)&g_eb[s + j + 4];
        uint2 v0 = zh2[i0.x * 32 + lane];
        uint2 v1 = zh2[i0.y * 32 + lane];
        uint2 v2 = zh2[i0.z * 32 + lane];
        uint2 v3 = zh2[i0.w * 32 + lane];
        uint2 v4 = zh2[i1.x * 32 + lane];
        uint2 v5 = zh2[i1.y * 32 + lane];
        uint2 v6 = zh2[i1.z * 32 + lane];
        uint2 v7 = zh2[i1.w * 32 + lane];
        __half2 gAx = __hadd2(__hadd2(u2h(v0.x), u2h(v1.x)), __hadd2(u2h(v2.x), u2h(v3.x)));
        __half2 gAy = __hadd2(__hadd2(u2h(v0.y), u2h(v1.y)), __hadd2(u2h(v2.y), u2h(v3.y)));
        __half2 gBx = __hadd2(__hadd2(u2h(v4.x), u2h(v5.x)), __hadd2(u2h(v6.x), u2h(v7.x)));
        __half2 gBy = __hadd2(__hadd2(u2h(v4.y), u2h(v5.y)), __hadd2(u2h(v6.y), u2h(v7.y)));
        float2 fa0 = __half22float2(gAx);
        float2 fa1 = __half22float2(gAy);
        float2 fb0 = __half22float2(gBx);
        float2 fb1 = __half22float2(gBy);
        aA.x += fa0.x; aA.y += fa0.y; aA.z += fa1.x; aA.w += fa1.y;
        aB.x += fb0.x; aB.y += fb0.y; aB.z += fb1.x; aB.w += fb1.y;
    }
    for (; j < n; j++) {
        uint2 v = zh2[g_eb[s + j] * 32 + lane];
        float2 f0 = __half22float2(u2h(v.x));
        float2 f1 = __half22float2(u2h(v.y));
        aA.x += f0.x; aA.y += f0.y; aA.z += f1.x; aA.w += f1.y;
    }
    __half2 h0 = __floats2half2_rn(self.x + aA.x + aB.x, self.y + aA.y + aB.y);
    __half2 h1 = __floats2half2_rn(self.z + aA.z + aB.z, self.w + aA.w + aB.w);
    uint2 hp;
    hp.x = *(unsigned*)&h0;
    hp.y = *(unsigned*)&h1;
    ((uint2*)outh)[gw * 32 + lane] = hp;
}

// ---------------- final aggregation (64 cols) -> fp32 out ----------------
__global__ void agg64_kernel(const __half* __restrict__ zh, float* __restrict__ out) {
    int gw = (blockIdx.x * blockDim.x + threadIdx.x) >> 5;
    if (gw >= NN) return;
    int lane = threadIdx.x & 31;
    const unsigned* zhu = (const unsigned*)zh;

    float2 self = __half22float2(u2h(zhu[gw * 32 + lane]));
    float2 aA = make_float2(0, 0);
    float2 aB = make_float2(0, 0);

    int n = g_cnt[gw];
    int s = gw * CAP;
    int j = 0;
    for (; j + 8 <= n; j += 8) {
        int4 i0 = *(const int4*)&g_eb[s + j];
        int4 i1 = *(const int4*)&g_eb[s + j + 4];
        unsigned v0 = zhu[i0.x * 32 + lane];
        unsigned v1 = zhu[i0.y * 32 + lane];
        unsigned v2 = zhu[i0.z * 32 + lane];
        unsigned v3 = zhu[i0.w * 32 + lane];
        unsigned v4 = zhu[i1.x * 32 + lane];
        unsigned v5 = zhu[i1.y * 32 + lane];
        unsigned v6 = zhu[i1.z * 32 + lane];
        unsigned v7 = zhu[i1.w * 32 + lane];
        __half2 gA = __hadd2(__hadd2(u2h(v0), u2h(v1)), __hadd2(u2h(v2), u2h(v3)));
        __half2 gB = __hadd2(__hadd2(u2h(v4), u2h(v5)), __hadd2(u2h(v6), u2h(v7)));
        float2 fa = __half22float2(gA);
        float2 fb = __half22float2(gB);
        aA.x += fa.x; aA.y += fa.y;
        aB.x += fb.x; aB.y += fb.y;
    }
    for (; j < n; j++) {
        float2 f = __half22float2(u2h(zhu[g_eb[s + j] * 32 + lane]));
        aA.x += f.x; aA.y += f.y;
    }
    float2 r;
    r.x = self.x + aA.x + aB.x;
    r.y = self.y + aA.y + aB.y;
    ((float2*)out)[gw * 32 + lane] = r;
}

// ---------------- launch ----------------
extern "C" void kernel_launch(void* const* d_in, const int* in_sizes, int n_in,
                              void* d_out, int out_size) {
    const float* feat = (const float*)d_in[0];
    const float* W0   = (const float*)d_in[1];
    const float* W1   = (const float*)d_in[2];
    const float* W2   = (const float*)d_in[3];
    const int*   src  = (const int*)d_in[4];
    const int*   dst  = (const int*)d_in[5];
    float*       out  = (float*)d_out;

    void *pzh0, *pzh1, *pzh2, *ph16, *pw1, *pw2;
    cudaGetSymbolAddress(&pzh0, g_zh0);
    cudaGetSymbolAddress(&pzh1, g_zh1);
    cudaGetSymbolAddress(&pzh2, g_zh2);
    cudaGetSymbolAddress(&ph16, g_h16);
    cudaGetSymbolAddress(&pw1, g_w1h);
    cudaGetSymbolAddress(&pw2, g_w2h);
    __half* h16 = (__half*)ph16;

    // prep: zero counters + W0 -> fp16
    prep_kernel<<<PREP_W0, 256>>>(W0);
    // scatter || layer-0 GEMM (fp16 W0) || W1/W2 cvt
    fused_l0_kernel<<<FUSED_BLOCKS, 256>>>(feat, W1, W2, src, dst);
    // layer 1: agg(zh0) -> h16 ; h16 @ W1 -> zh1
    agg128_kernel<<<AGG_BLOCKS, 256>>>((const __half*)pzh0, h16);
    gemm_mma_kernel<<<dim3(RB, 2), 256>>>(h16, (const __half*)pw1, (__half*)pzh1, NN, 128);
    // layer 2: agg(zh1) -> h16 ; h16 @ W2 -> zh2 (64 cols)
    agg128_kernel<<<AGG_BLOCKS, 256>>>((const __half*)pzh1, h16);
    gemm_mma_kernel<<<dim3(RB, 1), 256>>>(h16, (const __half*)pw2, (__half*)pzh2, NN, 64);
    // final aggregation -> fp32 out
    agg64_kernel<<<AGG_BLOCKS, 256>>>((const __half*)pzh2, out);
}